// round 11
// baseline (speedup 1.0000x reference)
#include <cuda_runtime.h>
#include <cuda_fp16.h>
#include <cstdint>

// LNN Euler-Lagrange residual: ReLU MLP => grad-of-grad vanishes under
// autodiff; output is exactly -dL/dq.
//
// mma.sync.m16n8k16 chain, register-only glue. fp16 hi/lo split.
// R11: pairwise chunk interleave — MMAs alternate between two independent
// accumulators c[nt]/c[nt+1] so dependent-accumulate latency can't
// serialize the tensor pipe. W3 folded into GEMM3's B (V = W2*diag(W3)),
// GEMM3 A = exact {0,1} mask -> 2-product chunks. Lean frame: 1 tile
// (16 rows) per warp, 3 CTAs/SM.

typedef uint32_t u32;

__device__ __forceinline__ u32 smem_addr(const void* p) {
    u32 a;
    asm("{ .reg .u64 t; cvta.to.shared.u64 t, %1; cvt.u32.u64 %0, t; }"
        : "=r"(a) : "l"(p));
    return a;
}
__device__ __forceinline__ u32 pack_f16x2(float x0, float x1) {   // lo=x0, hi=x1
    u32 r; asm("cvt.rn.f16x2.f32 %0, %1, %2;" : "=r"(r) : "f"(x1), "f"(x0));
    return r;
}
__device__ __forceinline__ float2 unpack_h2(u32 v) {
    float2 r;
    asm("{ .reg .b16 lo1, hi1; mov.b32 {lo1, hi1}, %2; "
        "cvt.f32.f16 %0, lo1; cvt.f32.f16 %1, hi1; }"
        : "=f"(r.x), "=f"(r.y) : "r"(v));
    return r;
}
__device__ __forceinline__ void split2(float x0, float x1, u32& hi, u32& lo) {
    hi = pack_f16x2(x0, x1);
    const float2 hf = unpack_h2(hi);
    lo = pack_f16x2(x0 - hf.x, x1 - hf.y);
}
__device__ __forceinline__ void ldm4(u32 r[4], u32 addr) {
    asm volatile("ldmatrix.sync.aligned.m8n8.x4.shared.b16 {%0,%1,%2,%3}, [%4];"
                 : "=r"(r[0]), "=r"(r[1]), "=r"(r[2]), "=r"(r[3]) : "r"(addr));
}
#define MMA(cc, aa, b0, b1)                                                  \
    asm volatile("mma.sync.aligned.m16n8k16.row.col.f32.f16.f16.f32 "        \
        "{%0,%1,%2,%3}, {%4,%5,%6,%7}, {%8,%9}, {%0,%1,%2,%3};"              \
        : "+f"((cc)[0]), "+f"((cc)[1]), "+f"((cc)[2]), "+f"((cc)[3])         \
        : "r"((aa)[0]), "r"((aa)[1]), "r"((aa)[2]), "r"((aa)[3]),            \
          "r"(b0), "r"(b1))

// smem: weight tiles [n][k] fp16, stride 72 halfs (144 B, conflict-free
// ldmatrix). hi + lo planes. V = W2 * diag(W3) for GEMM3.
#define OB_W1T_H 0
#define OB_W1T_L 9216
#define OB_W2T_H 18432
#define OB_W2T_L 27648
#define OB_V_H   36864
#define OB_V_L   46080
#define OB_W1Q_H 55296
#define OB_W1Q_L 59904
#define OB_B1    64512
#define OB_B2    64768
#define SMEM_TOTAL 65024

// Pair of 3-product chunks: two independent accumulator chains (c[nt0],
// c[nt0+1]) with their MMAs interleaved. Per-chain op order identical to
// the reference (kt asc; hi*hi, hi*lo, lo*hi per kt) -> bit-identical.
#define G_PAIR3(c, Ah, Al, BH, BL, nt0) do {                                 \
    u32 pa[4][4], pb[4][4];                                                  \
    ldm4(pa[0], (BH) + (nt0) * 1152);                                        \
    ldm4(pa[1], (BL) + (nt0) * 1152);                                        \
    ldm4(pa[2], (BH) + (nt0) * 1152 + 64);                                   \
    ldm4(pa[3], (BL) + (nt0) * 1152 + 64);                                   \
    ldm4(pb[0], (BH) + ((nt0) + 1) * 1152);                                  \
    ldm4(pb[1], (BL) + ((nt0) + 1) * 1152);                                  \
    ldm4(pb[2], (BH) + ((nt0) + 1) * 1152 + 64);                             \
    ldm4(pb[3], (BL) + ((nt0) + 1) * 1152 + 64);                             \
    float* cA = (c)[nt0];                                                    \
    float* cB = (c)[(nt0) + 1];                                              \
    cA[0]=0.f; cA[1]=0.f; cA[2]=0.f; cA[3]=0.f;                              \
    cB[0]=0.f; cB[1]=0.f; cB[2]=0.f; cB[3]=0.f;                              \
    MMA(cA, (Ah)[0], pa[0][0], pa[0][1]);                                    \
    MMA(cB, (Ah)[0], pb[0][0], pb[0][1]);                                    \
    MMA(cA, (Ah)[0], pa[1][0], pa[1][1]);                                    \
    MMA(cB, (Ah)[0], pb[1][0], pb[1][1]);                                    \
    MMA(cA, (Al)[0], pa[0][0], pa[0][1]);                                    \
    MMA(cB, (Al)[0], pb[0][0], pb[0][1]);                                    \
    MMA(cA, (Ah)[1], pa[0][2], pa[0][3]);                                    \
    MMA(cB, (Ah)[1], pb[0][2], pb[0][3]);                                    \
    MMA(cA, (Ah)[1], pa[1][2], pa[1][3]);                                    \
    MMA(cB, (Ah)[1], pb[1][2], pb[1][3]);                                    \
    MMA(cA, (Al)[1], pa[0][2], pa[0][3]);                                    \
    MMA(cB, (Al)[1], pb[0][2], pb[0][3]);                                    \
    MMA(cA, (Ah)[2], pa[2][0], pa[2][1]);                                    \
    MMA(cB, (Ah)[2], pb[2][0], pb[2][1]);                                    \
    MMA(cA, (Ah)[2], pa[3][0], pa[3][1]);                                    \
    MMA(cB, (Ah)[2], pb[3][0], pb[3][1]);                                    \
    MMA(cA, (Al)[2], pa[2][0], pa[2][1]);                                    \
    MMA(cB, (Al)[2], pb[2][0], pb[2][1]);                                    \
    MMA(cA, (Ah)[3], pa[2][2], pa[2][3]);                                    \
    MMA(cB, (Ah)[3], pb[2][2], pb[2][3]);                                    \
    MMA(cA, (Ah)[3], pa[3][2], pa[3][3]);                                    \
    MMA(cB, (Ah)[3], pb[3][2], pb[3][3]);                                    \
    MMA(cA, (Al)[3], pa[2][2], pa[2][3]);                                    \
    MMA(cB, (Al)[3], pb[2][2], pb[2][3]);                                    \
} while (0)

// Pair of 2-product chunks (A exact in fp16: products A*Bh + A*Bl).
#define G_PAIR2(c, Ah, BH, BL, nt0) do {                                     \
    u32 pa[4][4], pb[4][4];                                                  \
    ldm4(pa[0], (BH) + (nt0) * 1152);                                        \
    ldm4(pa[1], (BL) + (nt0) * 1152);                                        \
    ldm4(pa[2], (BH) + (nt0) * 1152 + 64);                                   \
    ldm4(pa[3], (BL) + (nt0) * 1152 + 64);                                   \
    ldm4(pb[0], (BH) + ((nt0) + 1) * 1152);                                  \
    ldm4(pb[1], (BL) + ((nt0) + 1) * 1152);                                  \
    ldm4(pb[2], (BH) + ((nt0) + 1) * 1152 + 64);                             \
    ldm4(pb[3], (BL) + ((nt0) + 1) * 1152 + 64);                             \
    float* cA = (c)[nt0];                                                    \
    float* cB = (c)[(nt0) + 1];                                              \
    cA[0]=0.f; cA[1]=0.f; cA[2]=0.f; cA[3]=0.f;                              \
    cB[0]=0.f; cB[1]=0.f; cB[2]=0.f; cB[3]=0.f;                              \
    MMA(cA, (Ah)[0], pa[0][0], pa[0][1]);                                    \
    MMA(cB, (Ah)[0], pb[0][0], pb[0][1]);                                    \
    MMA(cA, (Ah)[0], pa[1][0], pa[1][1]);                                    \
    MMA(cB, (Ah)[0], pb[1][0], pb[1][1]);                                    \
    MMA(cA, (Ah)[1], pa[0][2], pa[0][3]);                                    \
    MMA(cB, (Ah)[1], pb[0][2], pb[0][3]);                                    \
    MMA(cA, (Ah)[1], pa[1][2], pa[1][3]);                                    \
    MMA(cB, (Ah)[1], pb[1][2], pb[1][3]);                                    \
    MMA(cA, (Ah)[2], pa[2][0], pa[2][1]);                                    \
    MMA(cB, (Ah)[2], pb[2][0], pb[2][1]);                                    \
    MMA(cA, (Ah)[2], pa[3][0], pa[3][1]);                                    \
    MMA(cB, (Ah)[2], pb[3][0], pb[3][1]);                                    \
    MMA(cA, (Ah)[3], pa[2][2], pa[2][3]);                                    \
    MMA(cB, (Ah)[3], pb[2][2], pb[2][3]);                                    \
    MMA(cA, (Ah)[3], pa[3][2], pa[3][3]);                                    \
    MMA(cB, (Ah)[3], pb[3][2], pb[3][3]);                                    \
} while (0)

__global__ void __launch_bounds__(128, 3)
lnn_kernel(const float* __restrict__ X,
           const float* __restrict__ W1g, const float* __restrict__ b1g,
           const float* __restrict__ W2g, const float* __restrict__ b2g,
           const float* __restrict__ W3g,
           float* __restrict__ out, int B)
{
    extern __shared__ char smem[];
    __half* sh = reinterpret_cast<__half*>(smem);
    float* sb1 = reinterpret_cast<float*>(smem + OB_B1);
    float* sb2 = reinterpret_cast<float*>(smem + OB_B2);

    const int tid = threadIdx.x;
    const int wid = tid >> 5, lane = tid & 31;
    const int g = lane >> 2, tig = lane & 3;

    // ---- one-time weight staging: fp16 hi/lo planes, [n][k] stride 72 ----
    for (int idx = tid; idx < 4096; idx += 128) {
        const int r = idx >> 6, cc = idx & 63;
        {
            const float v = W1g[idx];                         // W1[r][cc]
            const __half hh = __float2half_rn(v);
            const __half hl = __float2half_rn(v - __half2float(hh));
            sh[(OB_W1T_H >> 1) + cc * 72 + r] = hh;           // W1T[n=cc][k=r]
            sh[(OB_W1T_L >> 1) + cc * 72 + r] = hl;
            if (r < 32) {                                     // W1q[n=r][k=cc]
                sh[(OB_W1Q_H >> 1) + r * 72 + cc] = hh;
                sh[(OB_W1Q_L >> 1) + r * 72 + cc] = hl;
            }
        }
        {
            const float v = W2g[idx];                         // W2[r][cc]
            const __half hh = __float2half_rn(v);
            const __half hl = __float2half_rn(v - __half2float(hh));
            sh[(OB_W2T_H >> 1) + cc * 72 + r] = hh;           // W2T[n=cc][k=r]
            sh[(OB_W2T_L >> 1) + cc * 72 + r] = hl;
            const float vv = v * W3g[cc];                     // V[n=r][k=cc]
            const __half vh = __float2half_rn(vv);
            const __half vl = __float2half_rn(vv - __half2float(vh));
            sh[(OB_V_H >> 1) + r * 72 + cc] = vh;
            sh[(OB_V_L >> 1) + r * 72 + cc] = vl;
        }
    }
    if (tid < 64) { sb1[tid] = b1g[tid]; sb2[tid] = b2g[tid]; }
    __syncthreads();

    const u32 sbase = smem_addr(smem);
    const u32 laneoff = (lane & 7) * 144 + (lane >> 3) * 16;
    const u32 bW1T_h = sbase + OB_W1T_H + laneoff, bW1T_l = sbase + OB_W1T_L + laneoff;
    const u32 bW2T_h = sbase + OB_W2T_H + laneoff, bW2T_l = sbase + OB_W2T_L + laneoff;
    const u32 bV_h   = sbase + OB_V_H   + laneoff, bV_l   = sbase + OB_V_L   + laneoff;
    const u32 bW1Q_h = sbase + OB_W1Q_H + laneoff, bW1Q_l = sbase + OB_W1Q_L + laneoff;

    const int ntiles = (B + 63) >> 6;          // 64 rows per CTA tile
    float c[8][4];
    u32 Ah[4][4], Al[4][4];

    for (int tile = blockIdx.x; tile < ntiles; tile += gridDim.x) {
        const int rowbase = tile * 64 + wid * 16;

        // ---- A = X fragments straight from gmem (fp32 -> hi/lo fp16) ----
        {
            int r0 = rowbase + g;
            int r1 = r0 + 8;
            if (r0 >= B) r0 = B - 1;
            if (r1 >= B) r1 = B - 1;
            const float* x0 = X + (size_t)r0 * 64 + 2 * tig;
            const float* x1 = X + (size_t)r1 * 64 + 2 * tig;
            #pragma unroll
            for (int kt = 0; kt < 4; kt++) {
                const float2 v00 = *reinterpret_cast<const float2*>(x0 + 16*kt);
                const float2 v01 = *reinterpret_cast<const float2*>(x0 + 16*kt + 8);
                const float2 v10 = *reinterpret_cast<const float2*>(x1 + 16*kt);
                const float2 v11 = *reinterpret_cast<const float2*>(x1 + 16*kt + 8);
                split2(v00.x, v00.y, Ah[kt][0], Al[kt][0]);
                split2(v10.x, v10.y, Ah[kt][1], Al[kt][1]);
                split2(v01.x, v01.y, Ah[kt][2], Al[kt][2]);
                split2(v11.x, v11.y, Ah[kt][3], Al[kt][3]);
            }
        }

        // ================= GEMM1: PRE1 = X @ W1 =================
        #pragma unroll
        for (int p = 0; p < 4; p++)
            G_PAIR3(c, Ah, Al, bW1T_h, bW1T_l, 2 * p);
        u32 m1 = 0u;
        #pragma unroll
        for (int nt = 0; nt < 8; nt++) {
            const float2 bv = *reinterpret_cast<const float2*>(sb1 + 8*nt + 2*tig);
            float p0 = c[nt][0] + bv.x;
            float p1 = c[nt][1] + bv.y;
            float p2 = c[nt][2] + bv.x;
            float p3 = c[nt][3] + bv.y;
            if (p0 > 0.0f) m1 |= 1u << (4*nt + 0); else p0 = 0.0f;
            if (p1 > 0.0f) m1 |= 1u << (4*nt + 1); else p1 = 0.0f;
            if (p2 > 0.0f) m1 |= 1u << (4*nt + 2); else p2 = 0.0f;
            if (p3 > 0.0f) m1 |= 1u << (4*nt + 3); else p3 = 0.0f;
            const int kt = nt >> 1, o = (nt & 1) << 1;
            split2(p0, p1, Ah[kt][o],     Al[kt][o]);
            split2(p2, p3, Ah[kt][o + 1], Al[kt][o + 1]);
        }

        // ================= GEMM2: PRE2 = H @ W2 =================
        #pragma unroll
        for (int p = 0; p < 4; p++)
            G_PAIR3(c, Ah, Al, bW2T_h, bW2T_l, 2 * p);
        #pragma unroll
        for (int nt = 0; nt < 8; nt++) {
            const float2 bv = *reinterpret_cast<const float2*>(sb2 + 8*nt + 2*tig);
            const float d0 = (c[nt][0] + bv.x > 0.0f) ? 1.0f : 0.0f;
            const float d1 = (c[nt][1] + bv.y > 0.0f) ? 1.0f : 0.0f;
            const float d2 = (c[nt][2] + bv.x > 0.0f) ? 1.0f : 0.0f;
            const float d3 = (c[nt][3] + bv.y > 0.0f) ? 1.0f : 0.0f;
            const int kt = nt >> 1, o = (nt & 1) << 1;
            Ah[kt][o]     = pack_f16x2(d0, d1);
            Ah[kt][o + 1] = pack_f16x2(d2, d3);
        }

        // ====== GEMM3: T = mask2 @ V^T (A exact, 2-product) ======
        #pragma unroll
        for (int p = 0; p < 4; p++)
            G_PAIR2(c, Ah, bV_h, bV_l, 2 * p);
        #pragma unroll
        for (int nt = 0; nt < 8; nt++) {
            const float t0 = ((m1 >> (4*nt + 0)) & 1u) ? -c[nt][0] : 0.0f;
            const float t1 = ((m1 >> (4*nt + 1)) & 1u) ? -c[nt][1] : 0.0f;
            const float t2 = ((m1 >> (4*nt + 2)) & 1u) ? -c[nt][2] : 0.0f;
            const float t3 = ((m1 >> (4*nt + 3)) & 1u) ? -c[nt][3] : 0.0f;
            const int kt = nt >> 1, o = (nt & 1) << 1;
            split2(t0, t1, Ah[kt][o],     Al[kt][o]);
            split2(t2, t3, Ah[kt][o + 1], Al[kt][o + 1]);
        }

        // ============ GEMM4: OUT = D1 @ W1q^T (N = 32) ============
        #pragma unroll
        for (int p = 0; p < 2; p++)
            G_PAIR3(c, Ah, Al, bW1Q_h, bW1Q_l, 2 * p);
        {
            const int r0 = rowbase + g;
            const int r1 = r0 + 8;
            #pragma unroll
            for (int nt = 0; nt < 4; nt++) {
                const int col = 8 * nt + 2 * tig;
                if (r0 < B)
                    *reinterpret_cast<float2*>(out + (size_t)r0 * 32 + col) =
                        make_float2(c[nt][0], c[nt][1]);
                if (r1 < B)
                    *reinterpret_cast<float2*>(out + (size_t)r1 * 32 + col) =
                        make_float2(c[nt][2], c[nt][3]);
            }
        }
    }
}

extern "C" void kernel_launch(void* const* d_in, const int* in_sizes, int n_in,
                              void* d_out, int out_size)
{
    const float* X  = (const float*)d_in[0];
    const float* W1 = (const float*)d_in[1];
    const float* b1 = (const float*)d_in[2];
    const float* W2 = (const float*)d_in[3];
    const float* b2 = (const float*)d_in[4];
    const float* W3 = (const float*)d_in[5];
    float* out = (float*)d_out;

    const int B = in_sizes[0] / 64;
    const int ntiles = (B + 63) / 64;
    int grid = 148 * 3;                 // persistent, 3 CTAs/SM
    if (grid > ntiles) grid = ntiles;

    cudaFuncSetAttribute(lnn_kernel,
                         cudaFuncAttributeMaxDynamicSharedMemorySize,
                         SMEM_TOTAL);
    lnn_kernel<<<grid, 128, SMEM_TOTAL>>>(X, W1, b1, W2, b2, W3, out, B);
}

// round 12
// speedup vs baseline: 1.0102x; 1.0102x over previous
#include <cuda_runtime.h>
#include <cuda_fp16.h>
#include <cstdint>

// LNN Euler-Lagrange residual: ReLU MLP => grad-of-grad vanishes under
// autodiff; output is exactly -dL/dq.
//
// mma.sync.m16n8k16 chain, register-only glue. fp16 hi/lo split.
// R12 hypothesis: f32-acc HMMA is rt=16/SMSP (measured across R7-R11);
// f16-acc HMMA may be rt=8. Main products (Ah*Bh) keep the f32
// accumulator; residual products (Ah*Bl + Al*Bh) accumulate in an f16
// accumulator and merge into the f32 result once per chunk. All lo
// planes are pre-scaled by 2048 (undone at merge) so residual products
// stay in fp16 normal range (no subnormal flush).

typedef uint32_t u32;

#define INV2048 4.8828125e-4f

__device__ __forceinline__ u32 smem_addr(const void* p) {
    u32 a;
    asm("{ .reg .u64 t; cvta.to.shared.u64 t, %1; cvt.u32.u64 %0, t; }"
        : "=r"(a) : "l"(p));
    return a;
}
__device__ __forceinline__ u32 pack_f16x2(float x0, float x1) {   // lo=x0, hi=x1
    u32 r; asm("cvt.rn.f16x2.f32 %0, %1, %2;" : "=r"(r) : "f"(x1), "f"(x0));
    return r;
}
__device__ __forceinline__ float2 unpack_h2(u32 v) {
    float2 r;
    asm("{ .reg .b16 lo1, hi1; mov.b32 {lo1, hi1}, %2; "
        "cvt.f32.f16 %0, lo1; cvt.f32.f16 %1, hi1; }"
        : "=f"(r.x), "=f"(r.y) : "r"(v));
    return r;
}
// fp32 pair -> fp16 hi word + fp16 residual word SCALED by 2048
__device__ __forceinline__ void split2s(float x0, float x1, u32& hi, u32& lo) {
    hi = pack_f16x2(x0, x1);
    const float2 hf = unpack_h2(hi);
    lo = pack_f16x2((x0 - hf.x) * 2048.0f, (x1 - hf.y) * 2048.0f);
}
__device__ __forceinline__ void ldm4(u32 r[4], u32 addr) {
    asm volatile("ldmatrix.sync.aligned.m8n8.x4.shared.b16 {%0,%1,%2,%3}, [%4];"
                 : "=r"(r[0]), "=r"(r[1]), "=r"(r[2]), "=r"(r[3]) : "r"(addr));
}
// f32-accumulator MMA (main products)
#define MMA(cc, aa, b0, b1)                                                  \
    asm volatile("mma.sync.aligned.m16n8k16.row.col.f32.f16.f16.f32 "        \
        "{%0,%1,%2,%3}, {%4,%5,%6,%7}, {%8,%9}, {%0,%1,%2,%3};"              \
        : "+f"((cc)[0]), "+f"((cc)[1]), "+f"((cc)[2]), "+f"((cc)[3])         \
        : "r"((aa)[0]), "r"((aa)[1]), "r"((aa)[2]), "r"((aa)[3]),            \
          "r"(b0), "r"(b1))
// f16-accumulator MMA (scaled residual products)
#define MMAH(hh, aa, b0, b1)                                                 \
    asm volatile("mma.sync.aligned.m16n8k16.row.col.f16.f16.f16.f16 "        \
        "{%0,%1}, {%2,%3,%4,%5}, {%6,%7}, {%0,%1};"                          \
        : "+r"((hh)[0]), "+r"((hh)[1])                                       \
        : "r"((aa)[0]), "r"((aa)[1]), "r"((aa)[2]), "r"((aa)[3]),            \
          "r"(b0), "r"(b1))

// smem: weight tiles [n][k] fp16, stride 72 halfs (144 B, conflict-free
// ldmatrix). hi planes exact; lo planes = (w - hi(w)) * 2048.
// V = W2 * diag(W3) for GEMM3.
#define OB_W1T_H 0
#define OB_W1T_L 9216
#define OB_W2T_H 18432
#define OB_W2T_L 27648
#define OB_V_H   36864
#define OB_V_L   46080
#define OB_W1Q_H 55296
#define OB_W1Q_L 59904
#define OB_B1    64512
#define OB_B2    64768
#define SMEM_TOTAL 65024

// 3-product chunk: main products f32-acc, residuals f16-acc (scaled).
#define G_CHUNK3(c, Ah, Al, BH, BL, nt) do {                                 \
    u32 b0h[4], b0l[4], b1h[4], b1l[4];                                      \
    ldm4(b0h, (BH) + (nt) * 1152);                                           \
    ldm4(b0l, (BL) + (nt) * 1152);                                           \
    ldm4(b1h, (BH) + (nt) * 1152 + 64);                                      \
    ldm4(b1l, (BL) + (nt) * 1152 + 64);                                      \
    float* cA = (c)[nt];                                                     \
    cA[0] = 0.f; cA[1] = 0.f; cA[2] = 0.f; cA[3] = 0.f;                      \
    u32 rh[2]; rh[0] = 0u; rh[1] = 0u;                                       \
    MMA(cA, (Ah)[0], b0h[0], b0h[1]);                                        \
    MMAH(rh, (Ah)[0], b0l[0], b0l[1]);                                       \
    MMAH(rh, (Al)[0], b0h[0], b0h[1]);                                       \
    MMA(cA, (Ah)[1], b0h[2], b0h[3]);                                        \
    MMAH(rh, (Ah)[1], b0l[2], b0l[3]);                                       \
    MMAH(rh, (Al)[1], b0h[2], b0h[3]);                                       \
    MMA(cA, (Ah)[2], b1h[0], b1h[1]);                                        \
    MMAH(rh, (Ah)[2], b1l[0], b1l[1]);                                       \
    MMAH(rh, (Al)[2], b1h[0], b1h[1]);                                       \
    MMA(cA, (Ah)[3], b1h[2], b1h[3]);                                        \
    MMAH(rh, (Ah)[3], b1l[2], b1l[3]);                                       \
    MMAH(rh, (Al)[3], b1h[2], b1h[3]);                                       \
    const float2 u0 = unpack_h2(rh[0]);                                      \
    const float2 u1 = unpack_h2(rh[1]);                                      \
    cA[0] = fmaf(u0.x, INV2048, cA[0]);                                      \
    cA[1] = fmaf(u0.y, INV2048, cA[1]);                                      \
    cA[2] = fmaf(u1.x, INV2048, cA[2]);                                      \
    cA[3] = fmaf(u1.y, INV2048, cA[3]);                                      \
} while (0)

// 2-product chunk (A exact in fp16): main f32-acc, B-residual f16-acc.
#define G_CHUNK2(c, Ah, BH, BL, nt) do {                                     \
    u32 b0h[4], b0l[4], b1h[4], b1l[4];                                      \
    ldm4(b0h, (BH) + (nt) * 1152);                                           \
    ldm4(b0l, (BL) + (nt) * 1152);                                           \
    ldm4(b1h, (BH) + (nt) * 1152 + 64);                                      \
    ldm4(b1l, (BL) + (nt) * 1152 + 64);                                      \
    float* cA = (c)[nt];                                                     \
    cA[0] = 0.f; cA[1] = 0.f; cA[2] = 0.f; cA[3] = 0.f;                      \
    u32 rh[2]; rh[0] = 0u; rh[1] = 0u;                                       \
    MMA(cA, (Ah)[0], b0h[0], b0h[1]);                                        \
    MMAH(rh, (Ah)[0], b0l[0], b0l[1]);                                       \
    MMA(cA, (Ah)[1], b0h[2], b0h[3]);                                        \
    MMAH(rh, (Ah)[1], b0l[2], b0l[3]);                                       \
    MMA(cA, (Ah)[2], b1h[0], b1h[1]);                                        \
    MMAH(rh, (Ah)[2], b1l[0], b1l[1]);                                       \
    MMA(cA, (Ah)[3], b1h[2], b1h[3]);                                        \
    MMAH(rh, (Ah)[3], b1l[2], b1l[3]);                                       \
    const float2 u0 = unpack_h2(rh[0]);                                      \
    const float2 u1 = unpack_h2(rh[1]);                                      \
    cA[0] = fmaf(u0.x, INV2048, cA[0]);                                      \
    cA[1] = fmaf(u0.y, INV2048, cA[1]);                                      \
    cA[2] = fmaf(u1.x, INV2048, cA[2]);                                      \
    cA[3] = fmaf(u1.y, INV2048, cA[3]);                                      \
} while (0)

__global__ void __launch_bounds__(128, 3)
lnn_kernel(const float* __restrict__ X,
           const float* __restrict__ W1g, const float* __restrict__ b1g,
           const float* __restrict__ W2g, const float* __restrict__ b2g,
           const float* __restrict__ W3g,
           float* __restrict__ out, int B)
{
    extern __shared__ char smem[];
    __half* sh = reinterpret_cast<__half*>(smem);
    float* sb1 = reinterpret_cast<float*>(smem + OB_B1);
    float* sb2 = reinterpret_cast<float*>(smem + OB_B2);

    const int tid = threadIdx.x;
    const int wid = tid >> 5, lane = tid & 31;
    const int g = lane >> 2, tig = lane & 3;

    // ---- one-time weight staging: hi plane + scaled lo plane ----
    for (int idx = tid; idx < 4096; idx += 128) {
        const int r = idx >> 6, cc = idx & 63;
        {
            const float v = W1g[idx];                         // W1[r][cc]
            const __half hh = __float2half_rn(v);
            const __half hl = __float2half_rn((v - __half2float(hh)) * 2048.0f);
            sh[(OB_W1T_H >> 1) + cc * 72 + r] = hh;           // W1T[n=cc][k=r]
            sh[(OB_W1T_L >> 1) + cc * 72 + r] = hl;
            if (r < 32) {                                     // W1q[n=r][k=cc]
                sh[(OB_W1Q_H >> 1) + r * 72 + cc] = hh;
                sh[(OB_W1Q_L >> 1) + r * 72 + cc] = hl;
            }
        }
        {
            const float v = W2g[idx];                         // W2[r][cc]
            const __half hh = __float2half_rn(v);
            const __half hl = __float2half_rn((v - __half2float(hh)) * 2048.0f);
            sh[(OB_W2T_H >> 1) + cc * 72 + r] = hh;           // W2T[n=cc][k=r]
            sh[(OB_W2T_L >> 1) + cc * 72 + r] = hl;
            const float vv = v * W3g[cc];                     // V[n=r][k=cc]
            const __half vh = __float2half_rn(vv);
            const __half vl = __float2half_rn((vv - __half2float(vh)) * 2048.0f);
            sh[(OB_V_H >> 1) + r * 72 + cc] = vh;
            sh[(OB_V_L >> 1) + r * 72 + cc] = vl;
        }
    }
    if (tid < 64) { sb1[tid] = b1g[tid]; sb2[tid] = b2g[tid]; }
    __syncthreads();

    const u32 sbase = smem_addr(smem);
    const u32 laneoff = (lane & 7) * 144 + (lane >> 3) * 16;
    const u32 bW1T_h = sbase + OB_W1T_H + laneoff, bW1T_l = sbase + OB_W1T_L + laneoff;
    const u32 bW2T_h = sbase + OB_W2T_H + laneoff, bW2T_l = sbase + OB_W2T_L + laneoff;
    const u32 bV_h   = sbase + OB_V_H   + laneoff, bV_l   = sbase + OB_V_L   + laneoff;
    const u32 bW1Q_h = sbase + OB_W1Q_H + laneoff, bW1Q_l = sbase + OB_W1Q_L + laneoff;

    const int ntiles = (B + 63) >> 6;          // 64 rows per CTA tile
    float c[8][4];
    u32 Ah[4][4], Al[4][4];

    for (int tile = blockIdx.x; tile < ntiles; tile += gridDim.x) {
        const int rowbase = tile * 64 + wid * 16;

        // ---- A = X fragments straight from gmem (fp32 -> hi + scaled lo) ----
        {
            int r0 = rowbase + g;
            int r1 = r0 + 8;
            if (r0 >= B) r0 = B - 1;
            if (r1 >= B) r1 = B - 1;
            const float* x0 = X + (size_t)r0 * 64 + 2 * tig;
            const float* x1 = X + (size_t)r1 * 64 + 2 * tig;
            #pragma unroll
            for (int kt = 0; kt < 4; kt++) {
                const float2 v00 = *reinterpret_cast<const float2*>(x0 + 16*kt);
                const float2 v01 = *reinterpret_cast<const float2*>(x0 + 16*kt + 8);
                const float2 v10 = *reinterpret_cast<const float2*>(x1 + 16*kt);
                const float2 v11 = *reinterpret_cast<const float2*>(x1 + 16*kt + 8);
                split2s(v00.x, v00.y, Ah[kt][0], Al[kt][0]);
                split2s(v10.x, v10.y, Ah[kt][1], Al[kt][1]);
                split2s(v01.x, v01.y, Ah[kt][2], Al[kt][2]);
                split2s(v11.x, v11.y, Ah[kt][3], Al[kt][3]);
            }
        }

        // ================= GEMM1: PRE1 = X @ W1 =================
        #pragma unroll
        for (int nt = 0; nt < 8; nt++)
            G_CHUNK3(c, Ah, Al, bW1T_h, bW1T_l, nt);
        u32 m1 = 0u;
        #pragma unroll
        for (int nt = 0; nt < 8; nt++) {
            const float2 bv = *reinterpret_cast<const float2*>(sb1 + 8*nt + 2*tig);
            float p0 = c[nt][0] + bv.x;
            float p1 = c[nt][1] + bv.y;
            float p2 = c[nt][2] + bv.x;
            float p3 = c[nt][3] + bv.y;
            if (p0 > 0.0f) m1 |= 1u << (4*nt + 0); else p0 = 0.0f;
            if (p1 > 0.0f) m1 |= 1u << (4*nt + 1); else p1 = 0.0f;
            if (p2 > 0.0f) m1 |= 1u << (4*nt + 2); else p2 = 0.0f;
            if (p3 > 0.0f) m1 |= 1u << (4*nt + 3); else p3 = 0.0f;
            const int kt = nt >> 1, o = (nt & 1) << 1;
            split2s(p0, p1, Ah[kt][o],     Al[kt][o]);
            split2s(p2, p3, Ah[kt][o + 1], Al[kt][o + 1]);
        }

        // ================= GEMM2: PRE2 = H @ W2 =================
        #pragma unroll
        for (int nt = 0; nt < 8; nt++)
            G_CHUNK3(c, Ah, Al, bW2T_h, bW2T_l, nt);
        #pragma unroll
        for (int nt = 0; nt < 8; nt++) {
            const float2 bv = *reinterpret_cast<const float2*>(sb2 + 8*nt + 2*tig);
            const float d0 = (c[nt][0] + bv.x > 0.0f) ? 1.0f : 0.0f;
            const float d1 = (c[nt][1] + bv.y > 0.0f) ? 1.0f : 0.0f;
            const float d2 = (c[nt][2] + bv.x > 0.0f) ? 1.0f : 0.0f;
            const float d3 = (c[nt][3] + bv.y > 0.0f) ? 1.0f : 0.0f;
            const int kt = nt >> 1, o = (nt & 1) << 1;
            Ah[kt][o]     = pack_f16x2(d0, d1);
            Ah[kt][o + 1] = pack_f16x2(d2, d3);
        }

        // ====== GEMM3: T = mask2 @ V^T (A exact, 2-product) ======
        #pragma unroll
        for (int nt = 0; nt < 8; nt++)
            G_CHUNK2(c, Ah, bV_h, bV_l, nt);
        #pragma unroll
        for (int nt = 0; nt < 8; nt++) {
            const float t0 = ((m1 >> (4*nt + 0)) & 1u) ? -c[nt][0] : 0.0f;
            const float t1 = ((m1 >> (4*nt + 1)) & 1u) ? -c[nt][1] : 0.0f;
            const float t2 = ((m1 >> (4*nt + 2)) & 1u) ? -c[nt][2] : 0.0f;
            const float t3 = ((m1 >> (4*nt + 3)) & 1u) ? -c[nt][3] : 0.0f;
            const int kt = nt >> 1, o = (nt & 1) << 1;
            split2s(t0, t1, Ah[kt][o],     Al[kt][o]);
            split2s(t2, t3, Ah[kt][o + 1], Al[kt][o + 1]);
        }

        // ============ GEMM4: OUT = D1 @ W1q^T (N = 32) ============
        #pragma unroll
        for (int nt = 0; nt < 4; nt++)
            G_CHUNK3(c, Ah, Al, bW1Q_h, bW1Q_l, nt);
        {
            const int r0 = rowbase + g;
            const int r1 = r0 + 8;
            #pragma unroll
            for (int nt = 0; nt < 4; nt++) {
                const int col = 8 * nt + 2 * tig;
                if (r0 < B)
                    *reinterpret_cast<float2*>(out + (size_t)r0 * 32 + col) =
                        make_float2(c[nt][0], c[nt][1]);
                if (r1 < B)
                    *reinterpret_cast<float2*>(out + (size_t)r1 * 32 + col) =
                        make_float2(c[nt][2], c[nt][3]);
            }
        }
    }
}

extern "C" void kernel_launch(void* const* d_in, const int* in_sizes, int n_in,
                              void* d_out, int out_size)
{
    const float* X  = (const float*)d_in[0];
    const float* W1 = (const float*)d_in[1];
    const float* b1 = (const float*)d_in[2];
    const float* W2 = (const float*)d_in[3];
    const float* b2 = (const float*)d_in[4];
    const float* W3 = (const float*)d_in[5];
    float* out = (float*)d_out;

    const int B = in_sizes[0] / 64;
    const int ntiles = (B + 63) / 64;
    int grid = 148 * 3;                 // persistent, 3 CTAs/SM
    if (grid > ntiles) grid = ntiles;

    cudaFuncSetAttribute(lnn_kernel,
                         cudaFuncAttributeMaxDynamicSharedMemorySize,
                         SMEM_TOTAL);
    lnn_kernel<<<grid, 128, SMEM_TOTAL>>>(X, W1, b1, W2, b2, W3, out, B);
}

// round 13
// speedup vs baseline: 1.1955x; 1.1835x over previous
#include <cuda_runtime.h>
#include <cuda_fp16.h>
#include <cstdint>

// LNN Euler-Lagrange residual: ReLU MLP => grad-of-grad vanishes under
// autodiff; output is exactly -dL/dq.
//
// mma.sync.m16n8k16 chain, register-only glue. Measured law on sm_103:
// every mma.sync costs 16 cyc/SMSP regardless of shape/accumulator, so
// minimize MMA count subject to the calibrated error model:
//   masks (G1, G2): flip-sensitive -> full 3-product split (96 + 96 MMAs)
//   smooth path (G3, G4): linear error -> fp16-RN is enough:
//     G3 = mask2 @ Vh^T, 1 product (32 MMAs)
//     G4 = fp16(t) @ (W1qh + W1ql), 2 products (32 MMAs)
// 256 MMAs per 16-row tile (was 304).

typedef uint32_t u32;

#define INV2048 4.8828125e-4f

__device__ __forceinline__ u32 smem_addr(const void* p) {
    u32 a;
    asm("{ .reg .u64 t; cvta.to.shared.u64 t, %1; cvt.u32.u64 %0, t; }"
        : "=r"(a) : "l"(p));
    return a;
}
__device__ __forceinline__ u32 pack_f16x2(float x0, float x1) {   // lo=x0, hi=x1
    u32 r; asm("cvt.rn.f16x2.f32 %0, %1, %2;" : "=r"(r) : "f"(x1), "f"(x0));
    return r;
}
__device__ __forceinline__ float2 unpack_h2(u32 v) {
    float2 r;
    asm("{ .reg .b16 lo1, hi1; mov.b32 {lo1, hi1}, %2; "
        "cvt.f32.f16 %0, lo1; cvt.f32.f16 %1, hi1; }"
        : "=f"(r.x), "=f"(r.y) : "r"(v));
    return r;
}
// fp32 pair -> fp16 hi word + fp16 residual word SCALED by 2048
__device__ __forceinline__ void split2s(float x0, float x1, u32& hi, u32& lo) {
    hi = pack_f16x2(x0, x1);
    const float2 hf = unpack_h2(hi);
    lo = pack_f16x2((x0 - hf.x) * 2048.0f, (x1 - hf.y) * 2048.0f);
}
__device__ __forceinline__ void ldm4(u32 r[4], u32 addr) {
    asm volatile("ldmatrix.sync.aligned.m8n8.x4.shared.b16 {%0,%1,%2,%3}, [%4];"
                 : "=r"(r[0]), "=r"(r[1]), "=r"(r[2]), "=r"(r[3]) : "r"(addr));
}
// f32-accumulator MMA (main products)
#define MMA(cc, aa, b0, b1)                                                  \
    asm volatile("mma.sync.aligned.m16n8k16.row.col.f32.f16.f16.f32 "        \
        "{%0,%1,%2,%3}, {%4,%5,%6,%7}, {%8,%9}, {%0,%1,%2,%3};"              \
        : "+f"((cc)[0]), "+f"((cc)[1]), "+f"((cc)[2]), "+f"((cc)[3])         \
        : "r"((aa)[0]), "r"((aa)[1]), "r"((aa)[2]), "r"((aa)[3]),            \
          "r"(b0), "r"(b1))
// f16-accumulator MMA (scaled residual products)
#define MMAH(hh, aa, b0, b1)                                                 \
    asm volatile("mma.sync.aligned.m16n8k16.row.col.f16.f16.f16.f16 "        \
        "{%0,%1}, {%2,%3,%4,%5}, {%6,%7}, {%0,%1};"                          \
        : "+r"((hh)[0]), "+r"((hh)[1])                                       \
        : "r"((aa)[0]), "r"((aa)[1]), "r"((aa)[2]), "r"((aa)[3]),            \
          "r"(b0), "r"(b1))

// smem: weight tiles [n][k] fp16, stride 72 halfs (144 B, conflict-free
// ldmatrix). hi planes exact; lo planes = (w - hi(w)) * 2048.
// V = W2 * diag(W3) for GEMM3 (hi plane only is used).
#define OB_W1T_H 0
#define OB_W1T_L 9216
#define OB_W2T_H 18432
#define OB_W2T_L 27648
#define OB_V_H   36864
#define OB_W1Q_H 46080
#define OB_W1Q_L 50688
#define OB_B1    55296
#define OB_B2    55552
#define SMEM_TOTAL 55808

// 3-product chunk: main products f32-acc, residuals f16-acc (scaled).
#define G_CHUNK3(c, Ah, Al, BH, BL, nt) do {                                 \
    u32 b0h[4], b0l[4], b1h[4], b1l[4];                                      \
    ldm4(b0h, (BH) + (nt) * 1152);                                           \
    ldm4(b0l, (BL) + (nt) * 1152);                                           \
    ldm4(b1h, (BH) + (nt) * 1152 + 64);                                      \
    ldm4(b1l, (BL) + (nt) * 1152 + 64);                                      \
    float* cA = (c)[nt];                                                     \
    cA[0] = 0.f; cA[1] = 0.f; cA[2] = 0.f; cA[3] = 0.f;                      \
    u32 rh[2]; rh[0] = 0u; rh[1] = 0u;                                       \
    MMA(cA, (Ah)[0], b0h[0], b0h[1]);                                        \
    MMAH(rh, (Ah)[0], b0l[0], b0l[1]);                                       \
    MMAH(rh, (Al)[0], b0h[0], b0h[1]);                                       \
    MMA(cA, (Ah)[1], b0h[2], b0h[3]);                                        \
    MMAH(rh, (Ah)[1], b0l[2], b0l[3]);                                       \
    MMAH(rh, (Al)[1], b0h[2], b0h[3]);                                       \
    MMA(cA, (Ah)[2], b1h[0], b1h[1]);                                        \
    MMAH(rh, (Ah)[2], b1l[0], b1l[1]);                                       \
    MMAH(rh, (Al)[2], b1h[0], b1h[1]);                                       \
    MMA(cA, (Ah)[3], b1h[2], b1h[3]);                                        \
    MMAH(rh, (Ah)[3], b1l[2], b1l[3]);                                       \
    MMAH(rh, (Al)[3], b1h[2], b1h[3]);                                       \
    const float2 u0 = unpack_h2(rh[0]);                                      \
    const float2 u1 = unpack_h2(rh[1]);                                      \
    cA[0] = fmaf(u0.x, INV2048, cA[0]);                                      \
    cA[1] = fmaf(u0.y, INV2048, cA[1]);                                      \
    cA[2] = fmaf(u1.x, INV2048, cA[2]);                                      \
    cA[3] = fmaf(u1.y, INV2048, cA[3]);                                      \
} while (0)

// 2-product chunk (A single fp16 plane): main f32-acc, B-residual f16-acc.
#define G_CHUNK2(c, Ah, BH, BL, nt) do {                                     \
    u32 b0h[4], b0l[4], b1h[4], b1l[4];                                      \
    ldm4(b0h, (BH) + (nt) * 1152);                                           \
    ldm4(b0l, (BL) + (nt) * 1152);                                           \
    ldm4(b1h, (BH) + (nt) * 1152 + 64);                                      \
    ldm4(b1l, (BL) + (nt) * 1152 + 64);                                      \
    float* cA = (c)[nt];                                                     \
    cA[0] = 0.f; cA[1] = 0.f; cA[2] = 0.f; cA[3] = 0.f;                      \
    u32 rh[2]; rh[0] = 0u; rh[1] = 0u;                                       \
    MMA(cA, (Ah)[0], b0h[0], b0h[1]);                                        \
    MMAH(rh, (Ah)[0], b0l[0], b0l[1]);                                       \
    MMA(cA, (Ah)[1], b0h[2], b0h[3]);                                        \
    MMAH(rh, (Ah)[1], b0l[2], b0l[3]);                                       \
    MMA(cA, (Ah)[2], b1h[0], b1h[1]);                                        \
    MMAH(rh, (Ah)[2], b1l[0], b1l[1]);                                       \
    MMA(cA, (Ah)[3], b1h[2], b1h[3]);                                        \
    MMAH(rh, (Ah)[3], b1l[2], b1l[3]);                                       \
    const float2 u0 = unpack_h2(rh[0]);                                      \
    const float2 u1 = unpack_h2(rh[1]);                                      \
    cA[0] = fmaf(u0.x, INV2048, cA[0]);                                      \
    cA[1] = fmaf(u0.y, INV2048, cA[1]);                                      \
    cA[2] = fmaf(u1.x, INV2048, cA[2]);                                      \
    cA[3] = fmaf(u1.y, INV2048, cA[3]);                                      \
} while (0)

// 1-product chunk (A exact mask, B hi plane only): 4 MMAs.
#define G_CHUNK1(c, Ah, BH, nt) do {                                         \
    u32 b0h[4], b1h[4];                                                      \
    ldm4(b0h, (BH) + (nt) * 1152);                                           \
    ldm4(b1h, (BH) + (nt) * 1152 + 64);                                      \
    float* cA = (c)[nt];                                                     \
    cA[0] = 0.f; cA[1] = 0.f; cA[2] = 0.f; cA[3] = 0.f;                      \
    MMA(cA, (Ah)[0], b0h[0], b0h[1]);                                        \
    MMA(cA, (Ah)[1], b0h[2], b0h[3]);                                        \
    MMA(cA, (Ah)[2], b1h[0], b1h[1]);                                        \
    MMA(cA, (Ah)[3], b1h[2], b1h[3]);                                        \
} while (0)

__global__ void __launch_bounds__(128, 3)
lnn_kernel(const float* __restrict__ X,
           const float* __restrict__ W1g, const float* __restrict__ b1g,
           const float* __restrict__ W2g, const float* __restrict__ b2g,
           const float* __restrict__ W3g,
           float* __restrict__ out, int B)
{
    extern __shared__ char smem[];
    __half* sh = reinterpret_cast<__half*>(smem);
    float* sb1 = reinterpret_cast<float*>(smem + OB_B1);
    float* sb2 = reinterpret_cast<float*>(smem + OB_B2);

    const int tid = threadIdx.x;
    const int wid = tid >> 5, lane = tid & 31;
    const int g = lane >> 2, tig = lane & 3;

    // ---- one-time weight staging: hi plane + scaled lo plane ----
    for (int idx = tid; idx < 4096; idx += 128) {
        const int r = idx >> 6, cc = idx & 63;
        {
            const float v = W1g[idx];                         // W1[r][cc]
            const __half hh = __float2half_rn(v);
            const __half hl = __float2half_rn((v - __half2float(hh)) * 2048.0f);
            sh[(OB_W1T_H >> 1) + cc * 72 + r] = hh;           // W1T[n=cc][k=r]
            sh[(OB_W1T_L >> 1) + cc * 72 + r] = hl;
            if (r < 32) {                                     // W1q[n=r][k=cc]
                sh[(OB_W1Q_H >> 1) + r * 72 + cc] = hh;
                sh[(OB_W1Q_L >> 1) + r * 72 + cc] = hl;
            }
        }
        {
            const float v = W2g[idx];                         // W2[r][cc]
            const __half hh = __float2half_rn(v);
            const __half hl = __float2half_rn((v - __half2float(hh)) * 2048.0f);
            sh[(OB_W2T_H >> 1) + cc * 72 + r] = hh;           // W2T[n=cc][k=r]
            sh[(OB_W2T_L >> 1) + cc * 72 + r] = hl;
            const float vv = v * W3g[cc];                     // V[n=r][k=cc]
            sh[(OB_V_H >> 1) + r * 72 + cc] = __float2half_rn(vv);
        }
    }
    if (tid < 64) { sb1[tid] = b1g[tid]; sb2[tid] = b2g[tid]; }
    __syncthreads();

    const u32 sbase = smem_addr(smem);
    const u32 laneoff = (lane & 7) * 144 + (lane >> 3) * 16;
    const u32 bW1T_h = sbase + OB_W1T_H + laneoff, bW1T_l = sbase + OB_W1T_L + laneoff;
    const u32 bW2T_h = sbase + OB_W2T_H + laneoff, bW2T_l = sbase + OB_W2T_L + laneoff;
    const u32 bV_h   = sbase + OB_V_H   + laneoff;
    const u32 bW1Q_h = sbase + OB_W1Q_H + laneoff, bW1Q_l = sbase + OB_W1Q_L + laneoff;

    const int ntiles = (B + 63) >> 6;          // 64 rows per CTA tile
    float c[8][4];
    u32 Ah[4][4], Al[4][4];

    for (int tile = blockIdx.x; tile < ntiles; tile += gridDim.x) {
        const int rowbase = tile * 64 + wid * 16;

        // ---- A = X fragments straight from gmem (fp32 -> hi + scaled lo) ----
        {
            int r0 = rowbase + g;
            int r1 = r0 + 8;
            if (r0 >= B) r0 = B - 1;
            if (r1 >= B) r1 = B - 1;
            const float* x0 = X + (size_t)r0 * 64 + 2 * tig;
            const float* x1 = X + (size_t)r1 * 64 + 2 * tig;
            #pragma unroll
            for (int kt = 0; kt < 4; kt++) {
                const float2 v00 = *reinterpret_cast<const float2*>(x0 + 16*kt);
                const float2 v01 = *reinterpret_cast<const float2*>(x0 + 16*kt + 8);
                const float2 v10 = *reinterpret_cast<const float2*>(x1 + 16*kt);
                const float2 v11 = *reinterpret_cast<const float2*>(x1 + 16*kt + 8);
                split2s(v00.x, v00.y, Ah[kt][0], Al[kt][0]);
                split2s(v10.x, v10.y, Ah[kt][1], Al[kt][1]);
                split2s(v01.x, v01.y, Ah[kt][2], Al[kt][2]);
                split2s(v11.x, v11.y, Ah[kt][3], Al[kt][3]);
            }
        }

        // ================= GEMM1: PRE1 = X @ W1 (3-product) =================
        #pragma unroll
        for (int nt = 0; nt < 8; nt++)
            G_CHUNK3(c, Ah, Al, bW1T_h, bW1T_l, nt);
        u32 m1 = 0u;
        #pragma unroll
        for (int nt = 0; nt < 8; nt++) {
            const float2 bv = *reinterpret_cast<const float2*>(sb1 + 8*nt + 2*tig);
            float p0 = c[nt][0] + bv.x;
            float p1 = c[nt][1] + bv.y;
            float p2 = c[nt][2] + bv.x;
            float p3 = c[nt][3] + bv.y;
            if (p0 > 0.0f) m1 |= 1u << (4*nt + 0); else p0 = 0.0f;
            if (p1 > 0.0f) m1 |= 1u << (4*nt + 1); else p1 = 0.0f;
            if (p2 > 0.0f) m1 |= 1u << (4*nt + 2); else p2 = 0.0f;
            if (p3 > 0.0f) m1 |= 1u << (4*nt + 3); else p3 = 0.0f;
            const int kt = nt >> 1, o = (nt & 1) << 1;
            split2s(p0, p1, Ah[kt][o],     Al[kt][o]);
            split2s(p2, p3, Ah[kt][o + 1], Al[kt][o + 1]);
        }

        // ================= GEMM2: PRE2 = H @ W2 (3-product) =================
        #pragma unroll
        for (int nt = 0; nt < 8; nt++)
            G_CHUNK3(c, Ah, Al, bW2T_h, bW2T_l, nt);
        #pragma unroll
        for (int nt = 0; nt < 8; nt++) {
            const float2 bv = *reinterpret_cast<const float2*>(sb2 + 8*nt + 2*tig);
            const float d0 = (c[nt][0] + bv.x > 0.0f) ? 1.0f : 0.0f;
            const float d1 = (c[nt][1] + bv.y > 0.0f) ? 1.0f : 0.0f;
            const float d2 = (c[nt][2] + bv.x > 0.0f) ? 1.0f : 0.0f;
            const float d3 = (c[nt][3] + bv.y > 0.0f) ? 1.0f : 0.0f;
            const int kt = nt >> 1, o = (nt & 1) << 1;
            Ah[kt][o]     = pack_f16x2(d0, d1);
            Ah[kt][o + 1] = pack_f16x2(d2, d3);
        }

        // ===== GEMM3: T = mask2 @ Vh^T (A exact, 1-product, smooth) =====
        #pragma unroll
        for (int nt = 0; nt < 8; nt++)
            G_CHUNK1(c, Ah, bV_h, nt);
        #pragma unroll
        for (int nt = 0; nt < 8; nt++) {
            const float t0 = ((m1 >> (4*nt + 0)) & 1u) ? -c[nt][0] : 0.0f;
            const float t1 = ((m1 >> (4*nt + 1)) & 1u) ? -c[nt][1] : 0.0f;
            const float t2 = ((m1 >> (4*nt + 2)) & 1u) ? -c[nt][2] : 0.0f;
            const float t3 = ((m1 >> (4*nt + 3)) & 1u) ? -c[nt][3] : 0.0f;
            const int kt = nt >> 1, o = (nt & 1) << 1;
            Ah[kt][o]     = pack_f16x2(t0, t1);
            Ah[kt][o + 1] = pack_f16x2(t2, t3);
        }

        // ==== GEMM4: OUT = fp16(t) @ W1q^T (N=32, 2-product, smooth) ====
        #pragma unroll
        for (int nt = 0; nt < 4; nt++)
            G_CHUNK2(c, Ah, bW1Q_h, bW1Q_l, nt);
        {
            const int r0 = rowbase + g;
            const int r1 = r0 + 8;
            #pragma unroll
            for (int nt = 0; nt < 4; nt++) {
                const int col = 8 * nt + 2 * tig;
                if (r0 < B)
                    *reinterpret_cast<float2*>(out + (size_t)r0 * 32 + col) =
                        make_float2(c[nt][0], c[nt][1]);
                if (r1 < B)
                    *reinterpret_cast<float2*>(out + (size_t)r1 * 32 + col) =
                        make_float2(c[nt][2], c[nt][3]);
            }
        }
    }
}

extern "C" void kernel_launch(void* const* d_in, const int* in_sizes, int n_in,
                              void* d_out, int out_size)
{
    const float* X  = (const float*)d_in[0];
    const float* W1 = (const float*)d_in[1];
    const float* b1 = (const float*)d_in[2];
    const float* W2 = (const float*)d_in[3];
    const float* b2 = (const float*)d_in[4];
    const float* W3 = (const float*)d_in[5];
    float* out = (float*)d_out;

    const int B = in_sizes[0] / 64;
    const int ntiles = (B + 63) / 64;
    int grid = 148 * 3;                 // persistent, 3 CTAs/SM
    if (grid > ntiles) grid = ntiles;

    cudaFuncSetAttribute(lnn_kernel,
                         cudaFuncAttributeMaxDynamicSharedMemorySize,
                         SMEM_TOTAL);
    lnn_kernel<<<grid, 128, SMEM_TOTAL>>>(X, W1, b1, W2, b2, W3, out, B);
}

// round 14
// speedup vs baseline: 1.2411x; 1.0381x over previous
#include <cuda_runtime.h>
#include <cuda_fp16.h>
#include <cstdint>

// LNN Euler-Lagrange residual: ReLU MLP => grad-of-grad vanishes under
// autodiff; output is exactly -dL/dq.
//
// mma.sync.m16n8k16 chain, register-only glue. Measured law on sm_103:
// every mma.sync costs 16 cyc/SMSP regardless of shape/accumulator, so
// minimize MMA count subject to the calibrated error model:
//   masks (G1, G2): flip-sensitive -> full 3-product split (96 + 96 MMAs)
//   smooth path (G3, G4): linear error -> fp16-RN is enough:
//     G3 = mask2 @ Vh^T, 1 product (32 MMAs)
//     G4 = fp16(t) @ W1qh^T, 1 product (16 MMAs)   [R14: dropped B-residual]
// 240 MMAs per 16-row tile (was 256).

typedef uint32_t u32;

#define INV2048 4.8828125e-4f

__device__ __forceinline__ u32 smem_addr(const void* p) {
    u32 a;
    asm("{ .reg .u64 t; cvta.to.shared.u64 t, %1; cvt.u32.u64 %0, t; }"
        : "=r"(a) : "l"(p));
    return a;
}
__device__ __forceinline__ u32 pack_f16x2(float x0, float x1) {   // lo=x0, hi=x1
    u32 r; asm("cvt.rn.f16x2.f32 %0, %1, %2;" : "=r"(r) : "f"(x1), "f"(x0));
    return r;
}
__device__ __forceinline__ float2 unpack_h2(u32 v) {
    float2 r;
    asm("{ .reg .b16 lo1, hi1; mov.b32 {lo1, hi1}, %2; "
        "cvt.f32.f16 %0, lo1; cvt.f32.f16 %1, hi1; }"
        : "=f"(r.x), "=f"(r.y) : "r"(v));
    return r;
}
// fp32 pair -> fp16 hi word + fp16 residual word SCALED by 2048
__device__ __forceinline__ void split2s(float x0, float x1, u32& hi, u32& lo) {
    hi = pack_f16x2(x0, x1);
    const float2 hf = unpack_h2(hi);
    lo = pack_f16x2((x0 - hf.x) * 2048.0f, (x1 - hf.y) * 2048.0f);
}
__device__ __forceinline__ void ldm4(u32 r[4], u32 addr) {
    asm volatile("ldmatrix.sync.aligned.m8n8.x4.shared.b16 {%0,%1,%2,%3}, [%4];"
                 : "=r"(r[0]), "=r"(r[1]), "=r"(r[2]), "=r"(r[3]) : "r"(addr));
}
// f32-accumulator MMA (main products)
#define MMA(cc, aa, b0, b1)                                                  \
    asm volatile("mma.sync.aligned.m16n8k16.row.col.f32.f16.f16.f32 "        \
        "{%0,%1,%2,%3}, {%4,%5,%6,%7}, {%8,%9}, {%0,%1,%2,%3};"              \
        : "+f"((cc)[0]), "+f"((cc)[1]), "+f"((cc)[2]), "+f"((cc)[3])         \
        : "r"((aa)[0]), "r"((aa)[1]), "r"((aa)[2]), "r"((aa)[3]),            \
          "r"(b0), "r"(b1))
// f16-accumulator MMA (scaled residual products)
#define MMAH(hh, aa, b0, b1)                                                 \
    asm volatile("mma.sync.aligned.m16n8k16.row.col.f16.f16.f16.f16 "        \
        "{%0,%1}, {%2,%3,%4,%5}, {%6,%7}, {%0,%1};"                          \
        : "+r"((hh)[0]), "+r"((hh)[1])                                       \
        : "r"((aa)[0]), "r"((aa)[1]), "r"((aa)[2]), "r"((aa)[3]),            \
          "r"(b0), "r"(b1))

// smem: weight tiles [n][k] fp16, stride 72 halfs (144 B, conflict-free
// ldmatrix). hi planes exact; lo planes = (w - hi(w)) * 2048.
// V = W2 * diag(W3) for GEMM3 (hi plane only).
#define OB_W1T_H 0
#define OB_W1T_L 9216
#define OB_W2T_H 18432
#define OB_W2T_L 27648
#define OB_V_H   36864
#define OB_W1Q_H 46080
#define OB_B1    50688
#define OB_B2    50944
#define SMEM_TOTAL 51200

// 3-product chunk: main products f32-acc, residuals f16-acc (scaled).
#define G_CHUNK3(c, Ah, Al, BH, BL, nt) do {                                 \
    u32 b0h[4], b0l[4], b1h[4], b1l[4];                                      \
    ldm4(b0h, (BH) + (nt) * 1152);                                           \
    ldm4(b0l, (BL) + (nt) * 1152);                                           \
    ldm4(b1h, (BH) + (nt) * 1152 + 64);                                      \
    ldm4(b1l, (BL) + (nt) * 1152 + 64);                                      \
    float* cA = (c)[nt];                                                     \
    cA[0] = 0.f; cA[1] = 0.f; cA[2] = 0.f; cA[3] = 0.f;                      \
    u32 rh[2]; rh[0] = 0u; rh[1] = 0u;                                       \
    MMA(cA, (Ah)[0], b0h[0], b0h[1]);                                        \
    MMAH(rh, (Ah)[0], b0l[0], b0l[1]);                                       \
    MMAH(rh, (Al)[0], b0h[0], b0h[1]);                                       \
    MMA(cA, (Ah)[1], b0h[2], b0h[3]);                                        \
    MMAH(rh, (Ah)[1], b0l[2], b0l[3]);                                       \
    MMAH(rh, (Al)[1], b0h[2], b0h[3]);                                       \
    MMA(cA, (Ah)[2], b1h[0], b1h[1]);                                        \
    MMAH(rh, (Ah)[2], b1l[0], b1l[1]);                                       \
    MMAH(rh, (Al)[2], b1h[0], b1h[1]);                                       \
    MMA(cA, (Ah)[3], b1h[2], b1h[3]);                                        \
    MMAH(rh, (Ah)[3], b1l[2], b1l[3]);                                       \
    MMAH(rh, (Al)[3], b1h[2], b1h[3]);                                       \
    const float2 u0 = unpack_h2(rh[0]);                                      \
    const float2 u1 = unpack_h2(rh[1]);                                      \
    cA[0] = fmaf(u0.x, INV2048, cA[0]);                                      \
    cA[1] = fmaf(u0.y, INV2048, cA[1]);                                      \
    cA[2] = fmaf(u1.x, INV2048, cA[2]);                                      \
    cA[3] = fmaf(u1.y, INV2048, cA[3]);                                      \
} while (0)

// 1-product chunk (hi planes only): 4 MMAs.
#define G_CHUNK1(c, Ah, BH, nt) do {                                         \
    u32 b0h[4], b1h[4];                                                      \
    ldm4(b0h, (BH) + (nt) * 1152);                                           \
    ldm4(b1h, (BH) + (nt) * 1152 + 64);                                      \
    float* cA = (c)[nt];                                                     \
    cA[0] = 0.f; cA[1] = 0.f; cA[2] = 0.f; cA[3] = 0.f;                      \
    MMA(cA, (Ah)[0], b0h[0], b0h[1]);                                        \
    MMA(cA, (Ah)[1], b0h[2], b0h[3]);                                        \
    MMA(cA, (Ah)[2], b1h[0], b1h[1]);                                        \
    MMA(cA, (Ah)[3], b1h[2], b1h[3]);                                        \
} while (0)

__global__ void __launch_bounds__(128, 3)
lnn_kernel(const float* __restrict__ X,
           const float* __restrict__ W1g, const float* __restrict__ b1g,
           const float* __restrict__ W2g, const float* __restrict__ b2g,
           const float* __restrict__ W3g,
           float* __restrict__ out, int B)
{
    extern __shared__ char smem[];
    __half* sh = reinterpret_cast<__half*>(smem);
    float* sb1 = reinterpret_cast<float*>(smem + OB_B1);
    float* sb2 = reinterpret_cast<float*>(smem + OB_B2);

    const int tid = threadIdx.x;
    const int wid = tid >> 5, lane = tid & 31;
    const int g = lane >> 2, tig = lane & 3;

    // ---- one-time weight staging: hi plane + scaled lo plane ----
    for (int idx = tid; idx < 4096; idx += 128) {
        const int r = idx >> 6, cc = idx & 63;
        {
            const float v = W1g[idx];                         // W1[r][cc]
            const __half hh = __float2half_rn(v);
            const __half hl = __float2half_rn((v - __half2float(hh)) * 2048.0f);
            sh[(OB_W1T_H >> 1) + cc * 72 + r] = hh;           // W1T[n=cc][k=r]
            sh[(OB_W1T_L >> 1) + cc * 72 + r] = hl;
            if (r < 32)                                       // W1q[n=r][k=cc]
                sh[(OB_W1Q_H >> 1) + r * 72 + cc] = hh;
        }
        {
            const float v = W2g[idx];                         // W2[r][cc]
            const __half hh = __float2half_rn(v);
            const __half hl = __float2half_rn((v - __half2float(hh)) * 2048.0f);
            sh[(OB_W2T_H >> 1) + cc * 72 + r] = hh;           // W2T[n=cc][k=r]
            sh[(OB_W2T_L >> 1) + cc * 72 + r] = hl;
            const float vv = v * W3g[cc];                     // V[n=r][k=cc]
            sh[(OB_V_H >> 1) + r * 72 + cc] = __float2half_rn(vv);
        }
    }
    if (tid < 64) { sb1[tid] = b1g[tid]; sb2[tid] = b2g[tid]; }
    __syncthreads();

    const u32 sbase = smem_addr(smem);
    const u32 laneoff = (lane & 7) * 144 + (lane >> 3) * 16;
    const u32 bW1T_h = sbase + OB_W1T_H + laneoff, bW1T_l = sbase + OB_W1T_L + laneoff;
    const u32 bW2T_h = sbase + OB_W2T_H + laneoff, bW2T_l = sbase + OB_W2T_L + laneoff;
    const u32 bV_h   = sbase + OB_V_H   + laneoff;
    const u32 bW1Q_h = sbase + OB_W1Q_H + laneoff;

    const int ntiles = (B + 63) >> 6;          // 64 rows per CTA tile
    float c[8][4];
    u32 Ah[4][4], Al[4][4];

    for (int tile = blockIdx.x; tile < ntiles; tile += gridDim.x) {
        const int rowbase = tile * 64 + wid * 16;

        // ---- A = X fragments straight from gmem (fp32 -> hi + scaled lo) ----
        {
            int r0 = rowbase + g;
            int r1 = r0 + 8;
            if (r0 >= B) r0 = B - 1;
            if (r1 >= B) r1 = B - 1;
            const float* x0 = X + (size_t)r0 * 64 + 2 * tig;
            const float* x1 = X + (size_t)r1 * 64 + 2 * tig;
            #pragma unroll
            for (int kt = 0; kt < 4; kt++) {
                const float2 v00 = *reinterpret_cast<const float2*>(x0 + 16*kt);
                const float2 v01 = *reinterpret_cast<const float2*>(x0 + 16*kt + 8);
                const float2 v10 = *reinterpret_cast<const float2*>(x1 + 16*kt);
                const float2 v11 = *reinterpret_cast<const float2*>(x1 + 16*kt + 8);
                split2s(v00.x, v00.y, Ah[kt][0], Al[kt][0]);
                split2s(v10.x, v10.y, Ah[kt][1], Al[kt][1]);
                split2s(v01.x, v01.y, Ah[kt][2], Al[kt][2]);
                split2s(v11.x, v11.y, Ah[kt][3], Al[kt][3]);
            }
        }

        // ================= GEMM1: PRE1 = X @ W1 (3-product) =================
        #pragma unroll
        for (int nt = 0; nt < 8; nt++)
            G_CHUNK3(c, Ah, Al, bW1T_h, bW1T_l, nt);
        u32 m1 = 0u;
        #pragma unroll
        for (int nt = 0; nt < 8; nt++) {
            const float2 bv = *reinterpret_cast<const float2*>(sb1 + 8*nt + 2*tig);
            float p0 = c[nt][0] + bv.x;
            float p1 = c[nt][1] + bv.y;
            float p2 = c[nt][2] + bv.x;
            float p3 = c[nt][3] + bv.y;
            if (p0 > 0.0f) m1 |= 1u << (4*nt + 0); else p0 = 0.0f;
            if (p1 > 0.0f) m1 |= 1u << (4*nt + 1); else p1 = 0.0f;
            if (p2 > 0.0f) m1 |= 1u << (4*nt + 2); else p2 = 0.0f;
            if (p3 > 0.0f) m1 |= 1u << (4*nt + 3); else p3 = 0.0f;
            const int kt = nt >> 1, o = (nt & 1) << 1;
            split2s(p0, p1, Ah[kt][o],     Al[kt][o]);
            split2s(p2, p3, Ah[kt][o + 1], Al[kt][o + 1]);
        }

        // ================= GEMM2: PRE2 = H @ W2 (3-product) =================
        #pragma unroll
        for (int nt = 0; nt < 8; nt++)
            G_CHUNK3(c, Ah, Al, bW2T_h, bW2T_l, nt);
        #pragma unroll
        for (int nt = 0; nt < 8; nt++) {
            const float2 bv = *reinterpret_cast<const float2*>(sb2 + 8*nt + 2*tig);
            const float d0 = (c[nt][0] + bv.x > 0.0f) ? 1.0f : 0.0f;
            const float d1 = (c[nt][1] + bv.y > 0.0f) ? 1.0f : 0.0f;
            const float d2 = (c[nt][2] + bv.x > 0.0f) ? 1.0f : 0.0f;
            const float d3 = (c[nt][3] + bv.y > 0.0f) ? 1.0f : 0.0f;
            const int kt = nt >> 1, o = (nt & 1) << 1;
            Ah[kt][o]     = pack_f16x2(d0, d1);
            Ah[kt][o + 1] = pack_f16x2(d2, d3);
        }

        // ===== GEMM3: T = mask2 @ Vh^T (A exact, 1-product, smooth) =====
        #pragma unroll
        for (int nt = 0; nt < 8; nt++)
            G_CHUNK1(c, Ah, bV_h, nt);
        #pragma unroll
        for (int nt = 0; nt < 8; nt++) {
            const float t0 = ((m1 >> (4*nt + 0)) & 1u) ? -c[nt][0] : 0.0f;
            const float t1 = ((m1 >> (4*nt + 1)) & 1u) ? -c[nt][1] : 0.0f;
            const float t2 = ((m1 >> (4*nt + 2)) & 1u) ? -c[nt][2] : 0.0f;
            const float t3 = ((m1 >> (4*nt + 3)) & 1u) ? -c[nt][3] : 0.0f;
            const int kt = nt >> 1, o = (nt & 1) << 1;
            Ah[kt][o]     = pack_f16x2(t0, t1);
            Ah[kt][o + 1] = pack_f16x2(t2, t3);
        }

        // ==== GEMM4: OUT = fp16(t) @ W1qh^T (N=32, 1-product, smooth) ====
        #pragma unroll
        for (int nt = 0; nt < 4; nt++)
            G_CHUNK1(c, Ah, bW1Q_h, nt);
        {
            const int r0 = rowbase + g;
            const int r1 = r0 + 8;
            #pragma unroll
            for (int nt = 0; nt < 4; nt++) {
                const int col = 8 * nt + 2 * tig;
                if (r0 < B)
                    *reinterpret_cast<float2*>(out + (size_t)r0 * 32 + col) =
                        make_float2(c[nt][0], c[nt][1]);
                if (r1 < B)
                    *reinterpret_cast<float2*>(out + (size_t)r1 * 32 + col) =
                        make_float2(c[nt][2], c[nt][3]);
            }
        }
    }
}

extern "C" void kernel_launch(void* const* d_in, const int* in_sizes, int n_in,
                              void* d_out, int out_size)
{
    const float* X  = (const float*)d_in[0];
    const float* W1 = (const float*)d_in[1];
    const float* b1 = (const float*)d_in[2];
    const float* W2 = (const float*)d_in[3];
    const float* b2 = (const float*)d_in[4];
    const float* W3 = (const float*)d_in[5];
    float* out = (float*)d_out;

    const int B = in_sizes[0] / 64;
    const int ntiles = (B + 63) / 64;
    int grid = 148 * 3;                 // persistent, 3 CTAs/SM
    if (grid > ntiles) grid = ntiles;

    cudaFuncSetAttribute(lnn_kernel,
                         cudaFuncAttributeMaxDynamicSharedMemorySize,
                         SMEM_TOTAL);
    lnn_kernel<<<grid, 128, SMEM_TOTAL>>>(X, W1, b1, W2, b2, W3, out, B);
}